// round 2
// baseline (speedup 1.0000x reference)
#include <cuda_runtime.h>
#include <cstdint>

#define BB 8
#define HH 256
#define WW 256
#define HW 65536

typedef unsigned long long u64;

__device__ __forceinline__ u64 ffma2(u64 a, u64 b, u64 c) {
    u64 d;
    asm("fma.rn.f32x2 %0, %1, %2, %3;" : "=l"(d) : "l"(a), "l"(b), "l"(c));
    return d;
}
__device__ __forceinline__ u64 pack2(float lo, float hi) {
    u64 r;
    asm("mov.b64 %0, {%1, %2};" : "=l"(r) : "f"(lo), "f"(hi));
    return r;
}
__device__ __forceinline__ float2 unpack2(u64 v) {
    float2 f;
    asm("mov.b64 {%0, %1}, %2;" : "=f"(f.x), "=f"(f.y) : "l"(v));
    return f;
}

// ---------------- scratch (device globals; no allocation) ----------------
__device__ __align__(128) float g_feat[(size_t)BB * 64 * HW];   // lrelu(conv1)
__device__ __align__(128) float g_dx  [(size_t)BB * 64 * HW];   // conv_c0 raw
__device__ __align__(128) float g_actv[(size_t)BB * HW * 128];  // NHWC!
__device__ __align__(128) float g_gb  [(size_t)BB * 128 * HW];  // gamma(0-63), beta(64-127)
__device__ __align__(128) float g_table[BB * 9 * 35 * 128];
__device__ __align__(128) float g_codes[BB * 35 * 64];
__device__ __align__(128) float g_sums [BB * 64 * 36];
__device__ __align__(128) float g_cnt  [BB * 36];
__device__ __align__(128) float g_stats[2 * BB * 64];           // mean, rstd
__device__ __align__(128) float2 g_w1[2 * 64 * 64 * 9];         // [half][ic][oc][k], {w,w}
__device__ __align__(128) float2 g_w2[2 * 128 * 64 * 9];

// ---------------- zero scratch accumulators ----------------
__global__ void k_zero() {
    int i = blockIdx.x * 256 + threadIdx.x;
    if (i < BB * 64 * 36) g_sums[i] = 0.f;
    if (i < BB * 36)      g_cnt[i]  = 0.f;
}

// ---------------- repack weights to [half][ic][oc][k] duplicated pairs ----------------
__global__ void k_repack(const float* __restrict__ wc, const float* __restrict__ wc0,
                         const float* __restrict__ wg, const float* __restrict__ wb) {
    int i = blockIdx.x * 256 + threadIdx.x;
    if (i < 73728) {  // g_w1: 2*64*64*9
        int h = i / 36864; int r = i % 36864;
        int ic = r / 576; int r2 = r % 576; int oc = r2 / 9; int k = r2 % 9;
        const float* src = h ? wc0 : wc;
        float v = src[(oc * 64 + ic) * 9 + k];
        g_w1[i] = make_float2(v, v);
    }
    if (i < 147456) { // g_w2: 2*128*64*9
        int h = i / 73728; int r = i % 73728;
        int ic = r / 576; int r2 = r % 576; int oc = r2 / 9; int k = r2 % 9;
        const float* src = h ? wb : wg;
        float v = src[(oc * 128 + ic) * 9 + k];
        g_w2[i] = make_float2(v, v);
    }
}

// ---------------- direct 3x3 conv, f32x2 packed, dual-output halves ----------------
// block: 256 thr; tile 32x8 px; thread: 8 px (2x4) x 8 oc.
template <int IC, bool NHWC>
__global__ void __launch_bounds__(256)
k_conv(const float* __restrict__ in, const float2* __restrict__ wpack,
       const float* __restrict__ bias0, const float* __restrict__ bias1,
       float* __restrict__ out0, float* __restrict__ out1,
       int act0, int act1, int ocb, int choff0, int choff1) {
    constexpr int ICC = 8;
    extern __shared__ float smem[];
    float* s_in = smem;                      // [ICC][10][36]
    u64*   s_w  = (u64*)(smem + ICC * 360);  // [ICC][64][9] duplicated pairs

    int b = blockIdx.z >> 1, half = blockIdx.z & 1;
    const float* bias = half ? bias1 : bias0;
    float* out = half ? out1 : out0;
    int act   = half ? act1 : act0;
    int choff = half ? choff1 : choff0;
    int x0 = blockIdx.x * 32, y0 = blockIdx.y * 8;
    int pxg = threadIdx.x & 31, ocg = threadIdx.x >> 5;
    int tx = (pxg & 7) * 4, ty = (pxg >> 3) * 2;

    u64 acc[8][2][2];
#pragma unroll
    for (int j = 0; j < 8; j++) {
        float bv = bias[ocg * 8 + j];
        u64 bp = pack2(bv, bv);
#pragma unroll
        for (int py = 0; py < 2; py++) {
            acc[j][py][0] = bp;
            acc[j][py][1] = bp;
        }
    }

    const u64* wbase = (const u64*)wpack + (size_t)half * IC * 576;

    for (int icc = 0; icc < IC; icc += ICC) {
        __syncthreads();
        const u64* wsrc = wbase + (size_t)icc * 576;
        for (int i = threadIdx.x; i < ICC * 576; i += 256) s_w[i] = wsrc[i];
        for (int i = threadIdx.x; i < ICC * 360; i += 256) {
            int ic, r, c;
            if (NHWC) { ic = i & 7; int j2 = i >> 3; r = j2 / 36; c = j2 % 36; }
            else      { ic = i / 360; int j2 = i % 360; r = j2 / 36; c = j2 % 36; }
            int gy = y0 - 1 + r, gx = x0 - 1 + c;
            float v = 0.f;
            if (c < 34 && (unsigned)gy < 256u && (unsigned)gx < 256u) {
                if (NHWC) v = in[((size_t)b * HW + gy * 256 + gx) * IC + icc + ic];
                else      v = in[((size_t)(b * IC + icc + ic)) * HW + gy * 256 + gx];
            }
            s_in[ic * 360 + r * 36 + c] = v;
        }
        __syncthreads();
#pragma unroll
        for (int ic = 0; ic < ICC; ic++) {
            // packed shifted input pairs: rp[r][m] = (row[m], row[m+1])
            u64 rp[4][5];
#pragma unroll
            for (int r = 0; r < 4; r++) {
                const float* row = &s_in[ic * 360 + (ty + r) * 36 + tx];
                float2 a = *(const float2*)(row + 0);
                float2 bq = *(const float2*)(row + 2);
                float2 cq = *(const float2*)(row + 4);
                rp[r][0] = pack2(a.x, a.y);
                rp[r][1] = pack2(a.y, bq.x);
                rp[r][2] = pack2(bq.x, bq.y);
                rp[r][3] = pack2(bq.y, cq.x);
                rp[r][4] = pack2(cq.x, cq.y);
            }
#pragma unroll
            for (int j = 0; j < 8; j++) {
                const u64* wp = &s_w[ic * 576 + (ocg * 8 + j) * 9];
                u64 w0 = wp[0], w1 = wp[1], w2 = wp[2];
                u64 w3 = wp[3], w4 = wp[4], w5 = wp[5];
                u64 w6 = wp[6], w7 = wp[7], w8 = wp[8];
#pragma unroll
                for (int py = 0; py < 2; py++)
#pragma unroll
                    for (int q = 0; q < 2; q++) {
                        u64 v = acc[j][py][q];
                        v = ffma2(w0, rp[py + 0][2 * q + 0], v);
                        v = ffma2(w1, rp[py + 0][2 * q + 1], v);
                        v = ffma2(w2, rp[py + 0][2 * q + 2], v);
                        v = ffma2(w3, rp[py + 1][2 * q + 0], v);
                        v = ffma2(w4, rp[py + 1][2 * q + 1], v);
                        v = ffma2(w5, rp[py + 1][2 * q + 2], v);
                        v = ffma2(w6, rp[py + 2][2 * q + 0], v);
                        v = ffma2(w7, rp[py + 2][2 * q + 1], v);
                        v = ffma2(w8, rp[py + 2][2 * q + 2], v);
                        acc[j][py][q] = v;
                    }
            }
        }
    }
#pragma unroll
    for (int j = 0; j < 8; j++) {
        int oc = ocg * 8 + j + choff;
#pragma unroll
        for (int py = 0; py < 2; py++) {
            int y = y0 + ty + py;
            float2 lo = unpack2(acc[j][py][0]);
            float2 hi = unpack2(acc[j][py][1]);
            float4 v;
            v.x = lo.x; v.y = lo.y; v.z = hi.x; v.w = hi.y;
            if (act == 1) {
                v.x = v.x >= 0.f ? v.x : 0.2f * v.x;
                v.y = v.y >= 0.f ? v.y : 0.2f * v.y;
                v.z = v.z >= 0.f ? v.z : 0.2f * v.z;
                v.w = v.w >= 0.f ? v.w : 0.2f * v.w;
            }
            *(float4*)&out[((size_t)(b * ocb + oc)) * HW + y * 256 + x0 + tx] = v;
        }
    }
}

// ---------------- instance-norm stats over g_dx ----------------
__global__ void k_stats() {
    int bc = blockIdx.x;  // 512 = B*64
    int tid = threadIdx.x;
    const float4* p = (const float4*)(g_dx + (size_t)bc * HW);
    float s = 0.f, s2 = 0.f;
    for (int i = tid; i < HW / 4; i += 256) {
        float4 v = p[i];
        s  += v.x + v.y + v.z + v.w;
        s2 += v.x * v.x + v.y * v.y + v.z * v.z + v.w * v.w;
    }
    __shared__ float rs[256], rq[256];
    rs[tid] = s; rq[tid] = s2;
    __syncthreads();
    for (int o = 128; o > 0; o >>= 1) {
        if (tid < o) { rs[tid] += rs[tid + o]; rq[tid] += rq[tid + o]; }
        __syncthreads();
    }
    if (tid == 0) {
        float m = rs[0] * (1.f / HW);
        float var = rq[0] * (1.f / HW) - m * m;
        g_stats[bc] = m;
        g_stats[512 + bc] = rsqrtf(var + 1e-5f);
    }
}

// ---------------- masked per-class mean pooling ----------------
__global__ void k_pool(const int* __restrict__ seg, const float* __restrict__ bg,
                       const float* __restrict__ mask) {
    __shared__ float s_sum[64 * 36];
    __shared__ float s_cnt[36];
    int tid = threadIdx.x;
    for (int i = tid; i < 64 * 36; i += 256) s_sum[i] = 0.f;
    if (tid < 36) s_cnt[tid] = 0.f;
    __syncthreads();
    int b = blockIdx.y;
    int lane = tid & 31, cg = tid >> 5;
    int base = blockIdx.x * 4096;
    for (int p0 = 0; p0 < 4096; p0 += 32) {
        int p = base + p0 + lane;
        int s = seg[b * HW + p];
        bool q = (bg[b * HW + p] * (1.f - mask[b * HW + p])) > 0.f;
        if (q && cg == 0) atomicAdd(&s_cnt[s], 1.f);
        if (q) {
#pragma unroll
            for (int cc = 0; cc < 8; cc++) {
                int c = cg + cc * 8;
                float f = g_feat[((size_t)(b * 64 + c)) * HW + p];
                atomicAdd(&s_sum[c * 36 + s], f);
            }
        }
    }
    __syncthreads();
    for (int i = tid; i < 64 * 36; i += 256) {
        float v = s_sum[i];
        if (v != 0.f) atomicAdd(&g_sums[b * 2304 + i], v);
    }
    if (tid < 36 && s_cnt[tid] != 0.f) atomicAdd(&g_cnt[b * 36 + tid], s_cnt[tid]);
}

// ---------------- codes (mean + keep mask) ----------------
__global__ void k_codes() {
    int i = blockIdx.x * 256 + threadIdx.x;
    if (i >= BB * 35 * 64) return;
    int b = i / (35 * 64); int s = (i / 64) % 35; int f = i & 63;
    float cnt = g_cnt[b * 36 + s];
    bool keep = !(s >= 24 && s <= 33);
    float v = 0.f;
    if (cnt > 0.f && keep) v = g_sums[b * 2304 + f * 36 + s] / cnt;
    g_codes[i] = v;  // [b][s][f]
}

// ---------------- fold codes + one-hot channels through w_sh -> table ----------------
// one block per (b,k): weights staged in smem, loop s
__global__ void k_table(const float* __restrict__ w_sh) {
    int b = blockIdx.x / 9, k = blockIdx.x % 9;
    int o = threadIdx.x;  // 128
    __shared__ float sw[64][128];
    __shared__ float sc[64];
    for (int f = 0; f < 64; f++) sw[f][o] = w_sh[(o * 99 + f) * 9 + k];
    for (int s = 0; s < 35; s++) {
        __syncthreads();
        if (o < 64) sc[o] = g_codes[(b * 35 + s) * 64 + o];
        __syncthreads();
        float acc = w_sh[(o * 99 + 64 + s) * 9 + k];
#pragma unroll 8
        for (int f = 0; f < 64; f++)
            acc = fmaf(sw[f][o], sc[f], acc);
        g_table[((b * 9 + k) * 35 + s) * 128 + o] = acc;
    }
}

// ---------------- actv = relu(b_sh + 3x3 table-gather conv), NHWC output ----------------
__global__ void k_actv(const int* __restrict__ seg, const float* __restrict__ bg,
                       const float* __restrict__ bsh) {
    __shared__ int ns[324];
    int b = blockIdx.z;
    int x0 = blockIdx.x * 16, y0 = blockIdx.y * 16;
    int tid = threadIdx.x;
    for (int i = tid; i < 324; i += 256) {
        int r = i / 18, c = i % 18;
        int gy = y0 - 1 + r, gx = x0 - 1 + c;
        int v = -1;
        if ((unsigned)gy < 256u && (unsigned)gx < 256u) {
            int p = gy * 256 + gx;
            if (bg[b * HW + p] > 0.f) v = seg[b * HW + p];
        }
        ns[i] = v;
    }
    __syncthreads();
    int oq = tid & 31, pg = tid >> 5;
    const float4* T4 = (const float4*)g_table + (size_t)b * 9 * 35 * 32;
    float4 bias = ((const float4*)bsh)[oq];
    for (int pp = pg * 32; pp < pg * 32 + 32; pp++) {
        int ly = pp >> 4, lx = pp & 15;
        float4 a = bias;
#pragma unroll
        for (int ky = 0; ky < 3; ky++)
#pragma unroll
            for (int kx = 0; kx < 3; kx++) {
                int idx = ns[(ly + ky) * 18 + lx + kx];
                if (idx >= 0) {
                    float4 t = T4[((ky * 3 + kx) * 35 + idx) * 32 + oq];
                    a.x += t.x; a.y += t.y; a.z += t.z; a.w += t.w;
                }
            }
        a.x = fmaxf(a.x, 0.f); a.y = fmaxf(a.y, 0.f);
        a.z = fmaxf(a.z, 0.f); a.w = fmaxf(a.w, 0.f);
        int gp = (y0 + ly) * 256 + x0 + lx;
        ((float4*)g_actv)[((size_t)b * HW + gp) * 32 + oq] = a;
    }
}

// ---------------- final: lrelu(instnorm(dx)*(1+gamma)+beta) ----------------
__global__ void k_final(float* __restrict__ out) {
    size_t gi = (size_t)blockIdx.x * 256 + threadIdx.x;  // float4 index
    size_t e = gi * 4;
    int b = (int)(e / ((size_t)64 * HW));
    int c = (int)((e / HW) & 63);
    size_t p = e % HW;
    float4 dx = ((const float4*)g_dx)[gi];
    float4 ga = ((const float4*)g_gb)[((size_t)(b * 128 + c) * HW + p) / 4];
    float4 be = ((const float4*)g_gb)[((size_t)(b * 128 + 64 + c) * HW + p) / 4];
    float m = g_stats[b * 64 + c], r = g_stats[512 + b * 64 + c];
    float4 o;
    {
        float v;
        v = (dx.x - m) * r * (1.f + ga.x) + be.x; o.x = v >= 0.f ? v : 0.2f * v;
        v = (dx.y - m) * r * (1.f + ga.y) + be.y; o.y = v >= 0.f ? v : 0.2f * v;
        v = (dx.z - m) * r * (1.f + ga.z) + be.z; o.z = v >= 0.f ? v : 0.2f * v;
        v = (dx.w - m) * r * (1.f + ga.w) + be.w; o.w = v >= 0.f ? v : 0.2f * v;
    }
    ((float4*)out)[gi] = o;
}

// ---------------- host ----------------
extern "C" void kernel_launch(void* const* d_in, const int* in_sizes, int n_in,
                              void* d_out, int out_size) {
    const float* featmap_in = (const float*)d_in[0];
    const int*   seg        = (const int*)  d_in[1];
    const float* bg         = (const float*)d_in[2];
    const float* mask       = (const float*)d_in[3];
    const float* w_conv     = (const float*)d_in[4];
    const float* b_conv     = (const float*)d_in[5];
    const float* w_c0       = (const float*)d_in[6];
    const float* b_c0       = (const float*)d_in[7];
    const float* w_sh       = (const float*)d_in[8];
    const float* b_sh       = (const float*)d_in[9];
    const float* w_g        = (const float*)d_in[10];
    const float* b_g        = (const float*)d_in[11];
    const float* w_b        = (const float*)d_in[12];
    const float* b_b        = (const float*)d_in[13];

    const int SMEM_BYTES = 8 * 360 * 4 + 8 * 576 * 8;  // 48384
    cudaFuncSetAttribute(k_conv<64, false>, cudaFuncAttributeMaxDynamicSharedMemorySize, SMEM_BYTES);
    cudaFuncSetAttribute(k_conv<128, true>, cudaFuncAttributeMaxDynamicSharedMemorySize, SMEM_BYTES);

    void *p_feat, *p_dx, *p_actv, *p_gb, *p_w1, *p_w2;
    cudaGetSymbolAddress(&p_feat, g_feat);
    cudaGetSymbolAddress(&p_dx,   g_dx);
    cudaGetSymbolAddress(&p_actv, g_actv);
    cudaGetSymbolAddress(&p_gb,   g_gb);
    cudaGetSymbolAddress(&p_w1,   g_w1);
    cudaGetSymbolAddress(&p_w2,   g_w2);

    k_zero<<<72, 256>>>();
    k_repack<<<576, 256>>>(w_conv, w_c0, w_g, w_b);

    // conv1 (lrelu -> g_feat) + conv_c0 (raw -> g_dx), fused over gridDim.z halves
    dim3 cgrid(8, 32, 16);
    k_conv<64, false><<<cgrid, 256, SMEM_BYTES>>>(
        featmap_in, (const float2*)p_w1, b_conv, b_c0,
        (float*)p_feat, (float*)p_dx, 1, 0, 64, 0, 0);

    k_stats<<<512, 256>>>();
    k_pool<<<dim3(16, 8), 256>>>(seg, bg, mask);
    k_codes<<<70, 256>>>();
    k_table<<<72, 128>>>(w_sh);
    k_actv<<<dim3(16, 16, 8), 256>>>(seg, bg, b_sh);

    // gamma (half0) + beta (half1) -> g_gb channels [0:64) / [64:128)
    k_conv<128, true><<<cgrid, 256, SMEM_BYTES>>>(
        (const float*)p_actv, (const float2*)p_w2, b_g, b_b,
        (float*)p_gb, (float*)p_gb, 0, 0, 128, 0, 64);

    k_final<<<32768, 256>>>((float*)d_out);
}

// round 3
// speedup vs baseline: 1.2804x; 1.2804x over previous
#include <cuda_runtime.h>
#include <cstdint>

#define BB 8
#define HH 256
#define WW 256
#define HW 65536

// ---------------- scratch (device globals; no allocation) ----------------
__device__ __align__(128) float g_feat[(size_t)BB * 64 * HW];   // lrelu(conv1)
__device__ __align__(128) float g_dx  [(size_t)BB * 64 * HW];   // conv_c0 raw
__device__ __align__(128) float g_actv[(size_t)BB * HW * 128];  // NHWC!
__device__ __align__(128) float g_gb  [(size_t)BB * 128 * HW];  // gamma(0-63), beta(64-127)
__device__ __align__(128) float g_table[BB * 9 * 35 * 128];
__device__ __align__(128) float g_codes[BB * 35 * 64];
__device__ __align__(128) float g_sums [BB * 64 * 36];
__device__ __align__(128) float g_cnt  [BB * 36];
__device__ __align__(128) float g_stats[2 * BB * 64];           // mean, rstd
__device__ __align__(128) float g_w1[2 * 64 * 64 * 12];         // [half][ic][oc][12] padded
__device__ __align__(128) float g_w2[2 * 128 * 64 * 12];

// ---------------- zero scratch accumulators ----------------
__global__ void k_zero() {
    int i = blockIdx.x * 256 + threadIdx.x;
    if (i < BB * 64 * 36) g_sums[i] = 0.f;
    if (i < BB * 36)      g_cnt[i]  = 0.f;
}

// ---------------- repack weights to [half][ic][oc][12] (taps padded 9->12) ----------------
__global__ void k_repack(const float* __restrict__ wc, const float* __restrict__ wc0,
                         const float* __restrict__ wg, const float* __restrict__ wb) {
    int i = blockIdx.x * 256 + threadIdx.x;
    if (i < 98304) {  // g_w1: 2*64*64*12
        int h = i / 49152; int r = i % 49152;
        int ic = r / 768; int r2 = r % 768; int oc = r2 / 12; int k = r2 % 12;
        const float* src = h ? wc0 : wc;
        g_w1[i] = (k < 9) ? src[(oc * 64 + ic) * 9 + k] : 0.f;
    }
    if (i < 196608) { // g_w2: 2*128*64*12
        int h = i / 98304; int r = i % 98304;
        int ic = r / 768; int r2 = r % 768; int oc = r2 / 12; int k = r2 % 12;
        const float* src = h ? wb : wg;
        g_w2[i] = (k < 9) ? src[(oc * 128 + ic) * 9 + k] : 0.f;
    }
}

// ---------------- direct 3x3 conv, dual-output (per gridDim.z half) ----------------
// block: 256 thr; tile 32x8 px; thread: 8 px (2x4) x 8 oc. OC per half = 64.
template <int IC, bool NHWC>
__global__ void __launch_bounds__(256, 2)
k_conv(const float* __restrict__ in, const float* __restrict__ wpack,
       const float* __restrict__ bias0, const float* __restrict__ bias1,
       float* __restrict__ out0, float* __restrict__ out1,
       int act0, int act1, int ocb, int choff0, int choff1) {
    constexpr int ICC = 16;
    extern __shared__ float smem[];
    float* s_in = smem;               // [ICC][10][36]
    float* s_w  = smem + ICC * 360;   // [ICC][64][12]

    int b = blockIdx.z >> 1, half = blockIdx.z & 1;
    const float* bias = half ? bias1 : bias0;
    float* out = half ? out1 : out0;
    int act   = half ? act1 : act0;
    int choff = half ? choff1 : choff0;
    int x0 = blockIdx.x * 32, y0 = blockIdx.y * 8;
    int pxg = threadIdx.x & 31, ocg = threadIdx.x >> 5;
    int tx = (pxg & 7) * 4, ty = (pxg >> 3) * 2;

    float acc[8][2][4];
#pragma unroll
    for (int j = 0; j < 8; j++) {
        float bv = bias[ocg * 8 + j];
#pragma unroll
        for (int py = 0; py < 2; py++)
#pragma unroll
            for (int px = 0; px < 4; px++) acc[j][py][px] = bv;
    }

    const float* wbase = wpack + (size_t)half * IC * 768;

    for (int icc = 0; icc < IC; icc += ICC) {
        __syncthreads();
        const float* wsrc = wbase + (size_t)icc * 768;
        for (int i = threadIdx.x; i < ICC * 768; i += 256) s_w[i] = wsrc[i];
        for (int i = threadIdx.x; i < ICC * 360; i += 256) {
            int ic, r, c;
            if (NHWC) { ic = i & 15; int j2 = i >> 4; r = j2 / 36; c = j2 % 36; }
            else      { ic = i / 360; int j2 = i % 360; r = j2 / 36; c = j2 % 36; }
            int gy = y0 - 1 + r, gx = x0 - 1 + c;
            float v = 0.f;
            if (c < 34 && (unsigned)gy < 256u && (unsigned)gx < 256u) {
                if (NHWC) v = in[((size_t)b * HW + gy * 256 + gx) * IC + icc + ic];
                else      v = in[((size_t)(b * IC + icc + ic)) * HW + gy * 256 + gx];
            }
            s_in[ic * 360 + r * 36 + c] = v;
        }
        __syncthreads();
#pragma unroll 2
        for (int ic = 0; ic < ICC; ic++) {
            float rin[4][6];
#pragma unroll
            for (int r = 0; r < 4; r++) {
                const float2* row = (const float2*)&s_in[ic * 360 + (ty + r) * 36 + tx];
                float2 p0 = row[0], p1 = row[1], p2 = row[2];
                rin[r][0] = p0.x; rin[r][1] = p0.y;
                rin[r][2] = p1.x; rin[r][3] = p1.y;
                rin[r][4] = p2.x; rin[r][5] = p2.y;
            }
#pragma unroll
            for (int j = 0; j < 8; j++) {
                const float4* wq = (const float4*)&s_w[(ic * 64 + ocg * 8 + j) * 12];
                float4 wa = wq[0];
                float4 wb = wq[1];
                float  w8 = ((const float*)wq)[8];
#pragma unroll
                for (int py = 0; py < 2; py++)
#pragma unroll
                    for (int px = 0; px < 4; px++) {
                        float v = acc[j][py][px];
                        v = fmaf(wa.x, rin[py + 0][px + 0], v);
                        v = fmaf(wa.y, rin[py + 0][px + 1], v);
                        v = fmaf(wa.z, rin[py + 0][px + 2], v);
                        v = fmaf(wa.w, rin[py + 1][px + 0], v);
                        v = fmaf(wb.x, rin[py + 1][px + 1], v);
                        v = fmaf(wb.y, rin[py + 1][px + 2], v);
                        v = fmaf(wb.z, rin[py + 2][px + 0], v);
                        v = fmaf(wb.w, rin[py + 2][px + 1], v);
                        v = fmaf(w8,   rin[py + 2][px + 2], v);
                        acc[j][py][px] = v;
                    }
            }
        }
    }
#pragma unroll
    for (int j = 0; j < 8; j++) {
        int oc = ocg * 8 + j + choff;
#pragma unroll
        for (int py = 0; py < 2; py++) {
            int y = y0 + ty + py;
            float4 v;
            v.x = acc[j][py][0]; v.y = acc[j][py][1];
            v.z = acc[j][py][2]; v.w = acc[j][py][3];
            if (act == 1) {
                v.x = v.x >= 0.f ? v.x : 0.2f * v.x;
                v.y = v.y >= 0.f ? v.y : 0.2f * v.y;
                v.z = v.z >= 0.f ? v.z : 0.2f * v.z;
                v.w = v.w >= 0.f ? v.w : 0.2f * v.w;
            }
            *(float4*)&out[((size_t)(b * ocb + oc)) * HW + y * 256 + x0 + tx] = v;
        }
    }
}

// ---------------- instance-norm stats over g_dx ----------------
__global__ void k_stats() {
    int bc = blockIdx.x;  // 512 = B*64
    int tid = threadIdx.x;
    const float4* p = (const float4*)(g_dx + (size_t)bc * HW);
    float s = 0.f, s2 = 0.f;
    for (int i = tid; i < HW / 4; i += 256) {
        float4 v = p[i];
        s  += v.x + v.y + v.z + v.w;
        s2 += v.x * v.x + v.y * v.y + v.z * v.z + v.w * v.w;
    }
    __shared__ float rs[256], rq[256];
    rs[tid] = s; rq[tid] = s2;
    __syncthreads();
    for (int o = 128; o > 0; o >>= 1) {
        if (tid < o) { rs[tid] += rs[tid + o]; rq[tid] += rq[tid + o]; }
        __syncthreads();
    }
    if (tid == 0) {
        float m = rs[0] * (1.f / HW);
        float var = rq[0] * (1.f / HW) - m * m;
        g_stats[bc] = m;
        g_stats[512 + bc] = rsqrtf(var + 1e-5f);
    }
}

// ---------------- masked per-class mean pooling ----------------
__global__ void k_pool(const int* __restrict__ seg, const float* __restrict__ bg,
                       const float* __restrict__ mask) {
    __shared__ float s_sum[64 * 36];
    __shared__ float s_cnt[36];
    int tid = threadIdx.x;
    for (int i = tid; i < 64 * 36; i += 256) s_sum[i] = 0.f;
    if (tid < 36) s_cnt[tid] = 0.f;
    __syncthreads();
    int b = blockIdx.y;
    int lane = tid & 31, cg = tid >> 5;
    int base = blockIdx.x * 4096;
    for (int p0 = 0; p0 < 4096; p0 += 32) {
        int p = base + p0 + lane;
        int s = seg[b * HW + p];
        bool q = (bg[b * HW + p] * (1.f - mask[b * HW + p])) > 0.f;
        if (q && cg == 0) atomicAdd(&s_cnt[s], 1.f);
        if (q) {
#pragma unroll
            for (int cc = 0; cc < 8; cc++) {
                int c = cg + cc * 8;
                float f = g_feat[((size_t)(b * 64 + c)) * HW + p];
                atomicAdd(&s_sum[c * 36 + s], f);
            }
        }
    }
    __syncthreads();
    for (int i = tid; i < 64 * 36; i += 256) {
        float v = s_sum[i];
        if (v != 0.f) atomicAdd(&g_sums[b * 2304 + i], v);
    }
    if (tid < 36 && s_cnt[tid] != 0.f) atomicAdd(&g_cnt[b * 36 + tid], s_cnt[tid]);
}

// ---------------- codes (mean + keep mask) ----------------
__global__ void k_codes() {
    int i = blockIdx.x * 256 + threadIdx.x;
    if (i >= BB * 35 * 64) return;
    int b = i / (35 * 64); int s = (i / 64) % 35; int f = i & 63;
    float cnt = g_cnt[b * 36 + s];
    bool keep = !(s >= 24 && s <= 33);
    float v = 0.f;
    if (cnt > 0.f && keep) v = g_sums[b * 2304 + f * 36 + s] / cnt;
    g_codes[i] = v;  // [b][s][f]
}

// ---------------- fold codes + one-hot channels through w_sh -> table ----------------
// one block per (b,k): weights staged in smem, loop s
__global__ void k_table(const float* __restrict__ w_sh) {
    int b = blockIdx.x / 9, k = blockIdx.x % 9;
    int o = threadIdx.x;  // 128
    __shared__ float sw[64][128];
    __shared__ float sc[64];
    for (int f = 0; f < 64; f++) sw[f][o] = w_sh[(o * 99 + f) * 9 + k];
    for (int s = 0; s < 35; s++) {
        __syncthreads();
        if (o < 64) sc[o] = g_codes[(b * 35 + s) * 64 + o];
        __syncthreads();
        float acc = w_sh[(o * 99 + 64 + s) * 9 + k];
#pragma unroll 8
        for (int f = 0; f < 64; f++)
            acc = fmaf(sw[f][o], sc[f], acc);
        g_table[((b * 9 + k) * 35 + s) * 128 + o] = acc;
    }
}

// ---------------- actv = relu(b_sh + 3x3 table-gather conv), NHWC output ----------------
__global__ void k_actv(const int* __restrict__ seg, const float* __restrict__ bg,
                       const float* __restrict__ bsh) {
    __shared__ int ns[324];
    int b = blockIdx.z;
    int x0 = blockIdx.x * 16, y0 = blockIdx.y * 16;
    int tid = threadIdx.x;
    for (int i = tid; i < 324; i += 256) {
        int r = i / 18, c = i % 18;
        int gy = y0 - 1 + r, gx = x0 - 1 + c;
        int v = -1;
        if ((unsigned)gy < 256u && (unsigned)gx < 256u) {
            int p = gy * 256 + gx;
            if (bg[b * HW + p] > 0.f) v = seg[b * HW + p];
        }
        ns[i] = v;
    }
    __syncthreads();
    int oq = tid & 31, pg = tid >> 5;
    const float4* T4 = (const float4*)g_table + (size_t)b * 9 * 35 * 32;
    float4 bias = ((const float4*)bsh)[oq];
    for (int pp = pg * 32; pp < pg * 32 + 32; pp++) {
        int ly = pp >> 4, lx = pp & 15;
        float4 a = bias;
#pragma unroll
        for (int ky = 0; ky < 3; ky++)
#pragma unroll
            for (int kx = 0; kx < 3; kx++) {
                int idx = ns[(ly + ky) * 18 + lx + kx];
                if (idx >= 0) {
                    float4 t = T4[((ky * 3 + kx) * 35 + idx) * 32 + oq];
                    a.x += t.x; a.y += t.y; a.z += t.z; a.w += t.w;
                }
            }
        a.x = fmaxf(a.x, 0.f); a.y = fmaxf(a.y, 0.f);
        a.z = fmaxf(a.z, 0.f); a.w = fmaxf(a.w, 0.f);
        int gp = (y0 + ly) * 256 + x0 + lx;
        ((float4*)g_actv)[((size_t)b * HW + gp) * 32 + oq] = a;
    }
}

// ---------------- final: lrelu(instnorm(dx)*(1+gamma)+beta) ----------------
__global__ void k_final(float* __restrict__ out) {
    size_t gi = (size_t)blockIdx.x * 256 + threadIdx.x;  // float4 index
    size_t e = gi * 4;
    int b = (int)(e / ((size_t)64 * HW));
    int c = (int)((e / HW) & 63);
    size_t p = e % HW;
    float4 dx = ((const float4*)g_dx)[gi];
    float4 ga = ((const float4*)g_gb)[((size_t)(b * 128 + c) * HW + p) / 4];
    float4 be = ((const float4*)g_gb)[((size_t)(b * 128 + 64 + c) * HW + p) / 4];
    float m = g_stats[b * 64 + c], r = g_stats[512 + b * 64 + c];
    float4 o;
    {
        float v;
        v = (dx.x - m) * r * (1.f + ga.x) + be.x; o.x = v >= 0.f ? v : 0.2f * v;
        v = (dx.y - m) * r * (1.f + ga.y) + be.y; o.y = v >= 0.f ? v : 0.2f * v;
        v = (dx.z - m) * r * (1.f + ga.z) + be.z; o.z = v >= 0.f ? v : 0.2f * v;
        v = (dx.w - m) * r * (1.f + ga.w) + be.w; o.w = v >= 0.f ? v : 0.2f * v;
    }
    ((float4*)out)[gi] = o;
}

// ---------------- host ----------------
extern "C" void kernel_launch(void* const* d_in, const int* in_sizes, int n_in,
                              void* d_out, int out_size) {
    const float* featmap_in = (const float*)d_in[0];
    const int*   seg        = (const int*)  d_in[1];
    const float* bg         = (const float*)d_in[2];
    const float* mask       = (const float*)d_in[3];
    const float* w_conv     = (const float*)d_in[4];
    const float* b_conv     = (const float*)d_in[5];
    const float* w_c0       = (const float*)d_in[6];
    const float* b_c0       = (const float*)d_in[7];
    const float* w_sh       = (const float*)d_in[8];
    const float* b_sh       = (const float*)d_in[9];
    const float* w_g        = (const float*)d_in[10];
    const float* b_g        = (const float*)d_in[11];
    const float* w_b        = (const float*)d_in[12];
    const float* b_b        = (const float*)d_in[13];

    const int SMEM_BYTES = 16 * 360 * 4 + 16 * 768 * 4;  // 23040 + 49152 = 72192
    cudaFuncSetAttribute(k_conv<64, false>, cudaFuncAttributeMaxDynamicSharedMemorySize, SMEM_BYTES);
    cudaFuncSetAttribute(k_conv<128, true>, cudaFuncAttributeMaxDynamicSharedMemorySize, SMEM_BYTES);

    void *p_feat, *p_dx, *p_actv, *p_gb, *p_w1, *p_w2;
    cudaGetSymbolAddress(&p_feat, g_feat);
    cudaGetSymbolAddress(&p_dx,   g_dx);
    cudaGetSymbolAddress(&p_actv, g_actv);
    cudaGetSymbolAddress(&p_gb,   g_gb);
    cudaGetSymbolAddress(&p_w1,   g_w1);
    cudaGetSymbolAddress(&p_w2,   g_w2);

    k_zero<<<72, 256>>>();
    k_repack<<<768, 256>>>(w_conv, w_c0, w_g, w_b);

    // conv1 (lrelu -> g_feat) + conv_c0 (raw -> g_dx), fused over gridDim.z halves
    dim3 cgrid(8, 32, 16);
    k_conv<64, false><<<cgrid, 256, SMEM_BYTES>>>(
        featmap_in, (const float*)p_w1, b_conv, b_c0,
        (float*)p_feat, (float*)p_dx, 1, 0, 64, 0, 0);

    k_stats<<<512, 256>>>();
    k_pool<<<dim3(16, 8), 256>>>(seg, bg, mask);
    k_codes<<<70, 256>>>();
    k_table<<<72, 128>>>(w_sh);
    k_actv<<<dim3(16, 16, 8), 256>>>(seg, bg, b_sh);

    // gamma (half0) + beta (half1) -> g_gb channels [0:64) / [64:128)
    k_conv<128, true><<<cgrid, 256, SMEM_BYTES>>>(
        (const float*)p_actv, (const float*)p_w2, b_g, b_b,
        (float*)p_gb, (float*)p_gb, 0, 0, 128, 0, 64);

    k_final<<<32768, 256>>>((float*)d_out);
}

// round 6
// speedup vs baseline: 2.0273x; 1.5834x over previous
#include <cuda_runtime.h>
#include <cuda_bf16.h>
#include <cstdint>

#define BB 8
#define HH 256
#define WW 256
#define HW 65536

// ==================== warp-MMA helpers (base PTX, no 'a' features) ====================
__device__ __forceinline__ uint32_t smem_u32(const void* p) {
    uint32_t a;
    asm("{ .reg .u64 t; cvta.to.shared.u64 t, %1; cvt.u32.u64 %0, t; }" : "=r"(a) : "l"(p));
    return a;
}
#define LDM4(r, addr)                                                              \
    asm volatile("ldmatrix.sync.aligned.m8n8.x4.shared.b16 {%0,%1,%2,%3}, [%4];"   \
        : "=r"((r)[0]), "=r"((r)[1]), "=r"((r)[2]), "=r"((r)[3]) : "r"(addr))
#define MMA(d, a, b0v, b1v)                                                        \
    asm volatile("mma.sync.aligned.m16n8k16.row.col.f32.bf16.bf16.f32 "            \
        "{%0,%1,%2,%3}, {%4,%5,%6,%7}, {%8,%9}, {%0,%1,%2,%3};"                    \
        : "+f"((d)[0]), "+f"((d)[1]), "+f"((d)[2]), "+f"((d)[3])                   \
        : "r"((a)[0]), "r"((a)[1]), "r"((a)[2]), "r"((a)[3]), "r"(b0v), "r"(b1v))

// ==================== scratch ====================
__device__ __align__(128) float g_feat[(size_t)BB * 64 * HW];
__device__ __align__(128) float g_dx  [(size_t)BB * 64 * HW];
__device__ __align__(128) __nv_bfloat16 g_actv_h[(size_t)BB * HW * 128];  // NHWC hi
__device__ __align__(128) __nv_bfloat16 g_actv_l[(size_t)BB * HW * 128];  // NHWC lo
__device__ __align__(128) float g_gb  [(size_t)BB * 128 * HW];            // gamma 0-63, beta 64-127
__device__ __align__(128) float g_table[BB * 9 * 35 * 128];
__device__ __align__(128) float g_codes[BB * 35 * 64];
__device__ __align__(128) float g_sums [BB * 64 * 36];
__device__ __align__(128) float g_cnt  [BB * 36];
__device__ __align__(128) float g_stats[2 * BB * 64];
__device__ __align__(128) float g_w1[2 * 64 * 64 * 9];                       // conv1 pack
__device__ __align__(128) __nv_bfloat16 g_w2m[9 * 2 * 2 * 128 * 64];         // [tap][kc][prec][oc][ic]

// ==================== small kernels ====================
__global__ void k_zero() {
    int i = blockIdx.x * 256 + threadIdx.x;
    if (i < BB * 64 * 36) g_sums[i] = 0.f;
    if (i < BB * 36)      g_cnt[i]  = 0.f;
}

__global__ void k_repack(const float* __restrict__ wc, const float* __restrict__ wc0) {
    int i = blockIdx.x * 256 + threadIdx.x;
    if (i < 73728) {  // 2*64*64*9
        int h = i / 36864; int r = i % 36864;
        int ic = r / 576; int r2 = r % 576; int oc = r2 / 9; int k = r2 % 9;
        const float* src = h ? wc0 : wc;
        g_w1[i] = src[(oc * 64 + ic) * 9 + k];
    }
}

// pack conv2 weights: [tap][kc][prec][oc(128: 0-63=gamma,64-127=beta)][ic(64)]
__global__ void k_wpack2(const float* __restrict__ wg, const float* __restrict__ wb) {
    int i = blockIdx.x * 256 + threadIdx.x;
    if (i >= 9 * 2 * 2 * 128 * 64) return;
    int ic   = i & 63;
    int oc   = (i >> 6) & 127;
    int prec = (i >> 13) & 1;
    int kc   = (i >> 14) & 1;
    int tap  = i >> 15;
    const float* src = (oc < 64) ? wg : wb;
    float wv = src[((oc & 63) * 128 + kc * 64 + ic) * 9 + tap];
    __nv_bfloat16 hi = __float2bfloat16(wv);
    g_w2m[i] = prec ? __float2bfloat16(wv - __bfloat162float(hi)) : hi;
}

// ==================== conv1 (scalar, known-good) ====================
template <int IC>
__global__ void __launch_bounds__(256, 2)
k_conv(const float* __restrict__ in, const float* __restrict__ wpack,
       const float* __restrict__ bias0, const float* __restrict__ bias1,
       float* __restrict__ out0, float* __restrict__ out1) {
    constexpr int ICC = 16;
    extern __shared__ float smem[];
    float* s_in = smem;               // [ICC][10][36]
    float* s_w  = smem + ICC * 360;   // [ICC][64][9]

    int b = blockIdx.z >> 1, half = blockIdx.z & 1;
    const float* bias = half ? bias1 : bias0;
    float* out = half ? out1 : out0;
    int act = half ? 0 : 1;
    int x0 = blockIdx.x * 32, y0 = blockIdx.y * 8;
    int pxg = threadIdx.x & 31, ocg = threadIdx.x >> 5;
    int tx = (pxg & 7) * 4, ty = (pxg >> 3) * 2;

    float acc[8][2][4];
#pragma unroll
    for (int j = 0; j < 8; j++) {
        float bv = bias[ocg * 8 + j];
#pragma unroll
        for (int py = 0; py < 2; py++)
#pragma unroll
            for (int px = 0; px < 4; px++) acc[j][py][px] = bv;
    }

    const float* wbase = wpack + (size_t)half * IC * 576;
    for (int icc = 0; icc < IC; icc += ICC) {
        __syncthreads();
        const float* wsrc = wbase + icc * 576;
        for (int i = threadIdx.x; i < ICC * 576; i += 256) s_w[i] = wsrc[i];
        for (int i = threadIdx.x; i < ICC * 360; i += 256) {
            int ic = i / 360; int j2 = i % 360; int r = j2 / 36, c = j2 % 36;
            int gy = y0 - 1 + r, gx = x0 - 1 + c;
            float v = 0.f;
            if (c < 34 && (unsigned)gy < 256u && (unsigned)gx < 256u)
                v = in[((size_t)(b * IC + icc + ic)) * HW + gy * 256 + gx];
            s_in[ic * 360 + r * 36 + c] = v;
        }
        __syncthreads();
#pragma unroll 2
        for (int ic = 0; ic < ICC; ic++) {
            float rin[4][6];
#pragma unroll
            for (int r = 0; r < 4; r++)
#pragma unroll
                for (int c = 0; c < 6; c++)
                    rin[r][c] = s_in[ic * 360 + (ty + r) * 36 + tx + c];
#pragma unroll
            for (int j = 0; j < 8; j++) {
                const float* wp = &s_w[ic * 576 + (ocg * 8 + j) * 9];
                float w0 = wp[0], w1 = wp[1], w2 = wp[2];
                float w3 = wp[3], w4 = wp[4], w5 = wp[5];
                float w6 = wp[6], w7 = wp[7], w8 = wp[8];
#pragma unroll
                for (int py = 0; py < 2; py++)
#pragma unroll
                    for (int px = 0; px < 4; px++) {
                        float v = acc[j][py][px];
                        v = fmaf(w0, rin[py + 0][px + 0], v);
                        v = fmaf(w1, rin[py + 0][px + 1], v);
                        v = fmaf(w2, rin[py + 0][px + 2], v);
                        v = fmaf(w3, rin[py + 1][px + 0], v);
                        v = fmaf(w4, rin[py + 1][px + 1], v);
                        v = fmaf(w5, rin[py + 1][px + 2], v);
                        v = fmaf(w6, rin[py + 2][px + 0], v);
                        v = fmaf(w7, rin[py + 2][px + 1], v);
                        v = fmaf(w8, rin[py + 2][px + 2], v);
                        acc[j][py][px] = v;
                    }
            }
        }
    }
#pragma unroll
    for (int j = 0; j < 8; j++) {
        int oc = ocg * 8 + j;
#pragma unroll
        for (int py = 0; py < 2; py++) {
            int y = y0 + ty + py;
            float4 v;
            v.x = acc[j][py][0]; v.y = acc[j][py][1];
            v.z = acc[j][py][2]; v.w = acc[j][py][3];
            if (act == 1) {
                v.x = v.x >= 0.f ? v.x : 0.2f * v.x;
                v.y = v.y >= 0.f ? v.y : 0.2f * v.y;
                v.z = v.z >= 0.f ? v.z : 0.2f * v.z;
                v.w = v.w >= 0.f ? v.w : 0.2f * v.w;
            }
            *(float4*)&out[((size_t)(b * 64 + oc)) * HW + y * 256 + x0 + tx] = v;
        }
    }
}

// ==================== conv2: warp-MMA bf16x3 implicit GEMM ====================
// CTA: (xblk 0..1, y 0..255, b 0..7) -> D[128 px][128 oc].
// smem: sA [prec][132 rows][72 bf16] (144B stride), sW [prec][128 oc][72 bf16]
static constexpr int SA_PREC = 132 * 144;        // 19008 B
static constexpr int SW_OFF  = 2 * SA_PREC;      // 38016
static constexpr int SW_PREC = 128 * 144;        // 18432
static constexpr int SMEM_MMA = SW_OFF + 2 * SW_PREC;  // 74880

__global__ void __launch_bounds__(256, 2)
k_conv2mma(const float* __restrict__ bg_, const float* __restrict__ bb_) {
    extern __shared__ __align__(1024) char sm[];
    uint32_t sa = smem_u32(sm);
    uint32_t sw = sa + SW_OFF;
    int tid = threadIdx.x;
    int w = tid >> 5, l = tid & 31;
    int x0 = blockIdx.x * 128, y = blockIdx.y, b = blockIdx.z;
    int mrow = (w & 3) * 32, ncol = (w >> 2) * 64;

    float acc[2][8][4];
#pragma unroll
    for (int mt = 0; mt < 2; mt++)
#pragma unroll
        for (int nt = 0; nt < 8; nt++)
#pragma unroll
            for (int e = 0; e < 4; e++) acc[mt][nt][e] = 0.f;

    for (int kc = 0; kc < 2; kc++) {
        for (int dy = 0; dy < 3; dy++) {
            __syncthreads();
            int iy = y + dy - 1;
            bool rowok = ((unsigned)iy < 256u);
            // stage A strip: 2 prec x 130 rows x 8 x 16B  (row = 64 bf16 = 128 B)
            for (int idx = tid; idx < 2080; idx += 256) {
                int prec = idx >= 1040; int e = idx - (prec ? 1040 : 0);
                int j = e >> 3, ch = e & 7;
                int x = x0 - 1 + j;
                uint4 v = make_uint4(0, 0, 0, 0);
                if (rowok && (unsigned)x < 256u) {
                    const __nv_bfloat16* src = prec ? g_actv_l : g_actv_h;
                    v = *(const uint4*)(src + (((size_t)b * HW + iy * 256 + x) << 7) + kc * 64 + ch * 8);
                }
                *(uint4*)(sm + prec * SA_PREC + j * 144 + ch * 16) = v;
            }
            for (int dx = 0; dx < 3; dx++) {
                int tap = dy * 3 + dx;
                __syncthreads();
                // stage W: 2 prec x 128 oc x 8 x 16B (contiguous in g_w2m)
                const uint4* wsrc = (const uint4*)g_w2m + (size_t)(tap * 2 + kc) * 2048;
                for (int idx = tid; idx < 2048; idx += 256) {
                    int prec = idx >> 10; int e = idx & 1023; int oc = e >> 3, ch = e & 7;
                    uint4 v = wsrc[idx];
                    *(uint4*)(sm + SW_OFF + prec * SW_PREC + oc * 144 + ch * 16) = v;
                }
                __syncthreads();

                uint32_t aBase = sa + (mrow + dx + (l & 15)) * 144 + (l >> 4) * 16;
                uint32_t bBase = sw + (ncol + ((l >> 4) << 3) + (l & 7)) * 144 + ((l >> 3) & 1) * 16;
#pragma unroll
                for (int ks = 0; ks < 4; ks++) {
                    uint32_t ah[2][4], al[2][4];
                    LDM4(ah[0], aBase + ks * 32);
                    LDM4(ah[1], aBase + 16 * 144 + ks * 32);
                    LDM4(al[0], aBase + SA_PREC + ks * 32);
                    LDM4(al[1], aBase + SA_PREC + 16 * 144 + ks * 32);
#pragma unroll
                    for (int np = 0; np < 4; np++) {
                        uint32_t bh[4], bl[4];
                        LDM4(bh, bBase + np * 16 * 144 + ks * 32);
                        LDM4(bl, bBase + SW_PREC + np * 16 * 144 + ks * 32);
#pragma unroll
                        for (int mt = 0; mt < 2; mt++) {
                            MMA(acc[mt][np * 2 + 0], ah[mt], bh[0], bh[1]);
                            MMA(acc[mt][np * 2 + 0], ah[mt], bl[0], bl[1]);
                            MMA(acc[mt][np * 2 + 0], al[mt], bh[0], bh[1]);
                            MMA(acc[mt][np * 2 + 1], ah[mt], bh[2], bh[3]);
                            MMA(acc[mt][np * 2 + 1], ah[mt], bl[2], bl[3]);
                            MMA(acc[mt][np * 2 + 1], al[mt], bh[2], bh[3]);
                        }
                    }
                }
            }
        }
    }

    // epilogue: D[px][oc] -> g_gb NCHW + bias
    int g = l >> 2, tg = l & 3;
#pragma unroll
    for (int nt = 0; nt < 8; nt++) {
        int oc0 = ncol + nt * 8 + tg * 2;
        float bias0 = (oc0 < 64) ? bg_[oc0] : bb_[oc0 - 64];
        float bias1 = (oc0 + 1 < 64) ? bg_[oc0 + 1] : bb_[oc0 - 63];
#pragma unroll
        for (int mt = 0; mt < 2; mt++) {
            int px = x0 + mrow + mt * 16 + g;
            size_t o0 = ((size_t)(b * 128 + oc0)) * HW + y * 256 + px;
            g_gb[o0]          = acc[mt][nt][0] + bias0;
            g_gb[o0 + HW]     = acc[mt][nt][1] + bias1;
            g_gb[o0 + 8]      = acc[mt][nt][2] + bias0;
            g_gb[o0 + HW + 8] = acc[mt][nt][3] + bias1;
        }
    }
}

// ==================== instance-norm stats ====================
__global__ void k_stats() {
    int bc = blockIdx.x;
    int tid = threadIdx.x;
    const float4* p = (const float4*)(g_dx + (size_t)bc * HW);
    float s = 0.f, s2 = 0.f;
    for (int i = tid; i < HW / 4; i += 256) {
        float4 v = p[i];
        s  += v.x + v.y + v.z + v.w;
        s2 += v.x * v.x + v.y * v.y + v.z * v.z + v.w * v.w;
    }
    __shared__ float rs[256], rq[256];
    rs[tid] = s; rq[tid] = s2;
    __syncthreads();
    for (int o = 128; o > 0; o >>= 1) {
        if (tid < o) { rs[tid] += rs[tid + o]; rq[tid] += rq[tid + o]; }
        __syncthreads();
    }
    if (tid == 0) {
        float m = rs[0] * (1.f / HW);
        float var = rq[0] * (1.f / HW) - m * m;
        g_stats[bc] = m;
        g_stats[512 + bc] = rsqrtf(var + 1e-5f);
    }
}

// ==================== masked per-class mean pooling ====================
__global__ void k_pool(const int* __restrict__ seg, const float* __restrict__ bg,
                       const float* __restrict__ mask) {
    __shared__ float s_sum[64 * 36];
    __shared__ float s_cnt[36];
    int tid = threadIdx.x;
    for (int i = tid; i < 64 * 36; i += 256) s_sum[i] = 0.f;
    if (tid < 36) s_cnt[tid] = 0.f;
    __syncthreads();
    int b = blockIdx.y;
    int lane = tid & 31, cg = tid >> 5;
    int base = blockIdx.x * 4096;
    for (int p0 = 0; p0 < 4096; p0 += 32) {
        int p = base + p0 + lane;
        int s = seg[b * HW + p];
        bool q = (bg[b * HW + p] * (1.f - mask[b * HW + p])) > 0.f;
        if (q && cg == 0) atomicAdd(&s_cnt[s], 1.f);
        if (q) {
#pragma unroll
            for (int cc = 0; cc < 8; cc++) {
                int c = cg + cc * 8;
                float f = g_feat[((size_t)(b * 64 + c)) * HW + p];
                atomicAdd(&s_sum[c * 36 + s], f);
            }
        }
    }
    __syncthreads();
    for (int i = tid; i < 64 * 36; i += 256) {
        float v = s_sum[i];
        if (v != 0.f) atomicAdd(&g_sums[b * 2304 + i], v);
    }
    if (tid < 36 && s_cnt[tid] != 0.f) atomicAdd(&g_cnt[b * 36 + tid], s_cnt[tid]);
}

__global__ void k_codes() {
    int i = blockIdx.x * 256 + threadIdx.x;
    if (i >= BB * 35 * 64) return;
    int b = i / (35 * 64); int s = (i / 64) % 35; int f = i & 63;
    float cnt = g_cnt[b * 36 + s];
    bool keep = !(s >= 24 && s <= 33);
    float v = 0.f;
    if (cnt > 0.f && keep) v = g_sums[b * 2304 + f * 36 + s] / cnt;
    g_codes[i] = v;
}

__global__ void k_table(const float* __restrict__ w_sh) {
    int b = blockIdx.x / 9, k = blockIdx.x % 9;
    int o = threadIdx.x;  // 128
    __shared__ float swt[64][128];
    __shared__ float sc[64];
    for (int f = 0; f < 64; f++) swt[f][o] = w_sh[(o * 99 + f) * 9 + k];
    for (int s = 0; s < 35; s++) {
        __syncthreads();
        if (o < 64) sc[o] = g_codes[(b * 35 + s) * 64 + o];
        __syncthreads();
        float acc = w_sh[(o * 99 + 64 + s) * 9 + k];
#pragma unroll 8
        for (int f = 0; f < 64; f++)
            acc = fmaf(swt[f][o], sc[f], acc);
        g_table[((b * 9 + k) * 35 + s) * 128 + o] = acc;
    }
}

// ---------------- actv = relu(b_sh + table conv) -> NHWC bf16 hi/lo ----------------
__global__ void k_actv(const int* __restrict__ seg, const float* __restrict__ bg,
                       const float* __restrict__ bsh) {
    __shared__ int ns[324];
    int b = blockIdx.z;
    int x0 = blockIdx.x * 16, y0 = blockIdx.y * 16;
    int tid = threadIdx.x;
    for (int i = tid; i < 324; i += 256) {
        int r = i / 18, c = i % 18;
        int gy = y0 - 1 + r, gx = x0 - 1 + c;
        int v = -1;
        if ((unsigned)gy < 256u && (unsigned)gx < 256u) {
            int p = gy * 256 + gx;
            if (bg[b * HW + p] > 0.f) v = seg[b * HW + p];
        }
        ns[i] = v;
    }
    __syncthreads();
    int oq = tid & 31, pg = tid >> 5;
    const float4* T4 = (const float4*)g_table + (size_t)b * 9 * 35 * 32;
    float4 bias = ((const float4*)bsh)[oq];
    for (int pp = pg * 32; pp < pg * 32 + 32; pp++) {
        int ly = pp >> 4, lx = pp & 15;
        float4 a = bias;
#pragma unroll
        for (int ky = 0; ky < 3; ky++)
#pragma unroll
            for (int kx = 0; kx < 3; kx++) {
                int idx = ns[(ly + ky) * 18 + lx + kx];
                if (idx >= 0) {
                    float4 t = T4[((ky * 3 + kx) * 35 + idx) * 32 + oq];
                    a.x += t.x; a.y += t.y; a.z += t.z; a.w += t.w;
                }
            }
        a.x = fmaxf(a.x, 0.f); a.y = fmaxf(a.y, 0.f);
        a.z = fmaxf(a.z, 0.f); a.w = fmaxf(a.w, 0.f);
        __nv_bfloat16 h0 = __float2bfloat16(a.x), h1 = __float2bfloat16(a.y);
        __nv_bfloat16 h2 = __float2bfloat16(a.z), h3 = __float2bfloat16(a.w);
        __nv_bfloat16 l0 = __float2bfloat16(a.x - __bfloat162float(h0));
        __nv_bfloat16 l1 = __float2bfloat16(a.y - __bfloat162float(h1));
        __nv_bfloat16 l2 = __float2bfloat16(a.z - __bfloat162float(h2));
        __nv_bfloat16 l3 = __float2bfloat16(a.w - __bfloat162float(h3));
        int gp = (y0 + ly) * 256 + x0 + lx;
        size_t base = (((size_t)b * HW + gp) << 7) + oq * 4;
        uint2 hv, lv;
        hv.x = (uint32_t)__bfloat16_as_ushort(h0) | ((uint32_t)__bfloat16_as_ushort(h1) << 16);
        hv.y = (uint32_t)__bfloat16_as_ushort(h2) | ((uint32_t)__bfloat16_as_ushort(h3) << 16);
        lv.x = (uint32_t)__bfloat16_as_ushort(l0) | ((uint32_t)__bfloat16_as_ushort(l1) << 16);
        lv.y = (uint32_t)__bfloat16_as_ushort(l2) | ((uint32_t)__bfloat16_as_ushort(l3) << 16);
        *(uint2*)(g_actv_h + base) = hv;
        *(uint2*)(g_actv_l + base) = lv;
    }
}

// ---------------- final ----------------
__global__ void k_final(float* __restrict__ out) {
    size_t gi = (size_t)blockIdx.x * 256 + threadIdx.x;
    size_t e = gi * 4;
    int b = (int)(e / ((size_t)64 * HW));
    int c = (int)((e / HW) & 63);
    size_t p = e % HW;
    float4 dx = ((const float4*)g_dx)[gi];
    float4 ga = ((const float4*)g_gb)[((size_t)(b * 128 + c) * HW + p) / 4];
    float4 be = ((const float4*)g_gb)[((size_t)(b * 128 + 64 + c) * HW + p) / 4];
    float m = g_stats[b * 64 + c], r = g_stats[512 + b * 64 + c];
    float4 o;
    float v;
    v = (dx.x - m) * r * (1.f + ga.x) + be.x; o.x = v >= 0.f ? v : 0.2f * v;
    v = (dx.y - m) * r * (1.f + ga.y) + be.y; o.y = v >= 0.f ? v : 0.2f * v;
    v = (dx.z - m) * r * (1.f + ga.z) + be.z; o.z = v >= 0.f ? v : 0.2f * v;
    v = (dx.w - m) * r * (1.f + ga.w) + be.w; o.w = v >= 0.f ? v : 0.2f * v;
    ((float4*)out)[gi] = o;
}

// ==================== host ====================
extern "C" void kernel_launch(void* const* d_in, const int* in_sizes, int n_in,
                              void* d_out, int out_size) {
    const float* featmap_in = (const float*)d_in[0];
    const int*   seg        = (const int*)  d_in[1];
    const float* bg         = (const float*)d_in[2];
    const float* mask       = (const float*)d_in[3];
    const float* w_conv     = (const float*)d_in[4];
    const float* b_conv     = (const float*)d_in[5];
    const float* w_c0       = (const float*)d_in[6];
    const float* b_c0       = (const float*)d_in[7];
    const float* w_sh       = (const float*)d_in[8];
    const float* b_sh       = (const float*)d_in[9];
    const float* w_g        = (const float*)d_in[10];
    const float* b_g        = (const float*)d_in[11];
    const float* w_b        = (const float*)d_in[12];
    const float* b_b        = (const float*)d_in[13];

    const int SMEM_C1 = (16 * 360 + 16 * 576) * 4;  // 59904
    cudaFuncSetAttribute(k_conv<64>, cudaFuncAttributeMaxDynamicSharedMemorySize, SMEM_C1);
    cudaFuncSetAttribute(k_conv2mma, cudaFuncAttributeMaxDynamicSharedMemorySize, SMEM_MMA);

    void *p_feat, *p_dx, *p_w1;
    cudaGetSymbolAddress(&p_feat, g_feat);
    cudaGetSymbolAddress(&p_dx,   g_dx);
    cudaGetSymbolAddress(&p_w1,   g_w1);

    k_zero<<<72, 256>>>();
    k_repack<<<288, 256>>>(w_conv, w_c0);
    k_wpack2<<<1152, 256>>>(w_g, w_b);

    // conv1 (lrelu -> g_feat) + conv_c0 (raw -> g_dx)
    dim3 cgrid(8, 32, 16);
    k_conv<64><<<cgrid, 256, SMEM_C1>>>(
        featmap_in, (const float*)p_w1, b_conv, b_c0,
        (float*)p_feat, (float*)p_dx);

    k_stats<<<512, 256>>>();
    k_pool<<<dim3(16, 8), 256>>>(seg, bg, mask);
    k_codes<<<70, 256>>>();
    k_table<<<72, 128>>>(w_sh);
    k_actv<<<dim3(16, 16, 8), 256>>>(seg, bg, b_sh);

    // gamma/beta via warp-MMA bf16x3
    k_conv2mma<<<dim3(2, 256, 8), 256, SMEM_MMA>>>(b_g, b_b);

    k_final<<<32768, 256>>>((float*)d_out);
}

// round 7
// speedup vs baseline: 2.7609x; 1.3619x over previous
#include <cuda_runtime.h>
#include <cuda_bf16.h>
#include <cstdint>

#define BB 8
#define HH 256
#define WW 256
#define HW 65536

// ==================== warp-MMA helpers (base PTX, no 'a' features) ====================
__device__ __forceinline__ uint32_t smem_u32(const void* p) {
    uint32_t a;
    asm("{ .reg .u64 t; cvta.to.shared.u64 t, %1; cvt.u32.u64 %0, t; }" : "=r"(a) : "l"(p));
    return a;
}
#define LDM4(r, addr)                                                              \
    asm volatile("ldmatrix.sync.aligned.m8n8.x4.shared.b16 {%0,%1,%2,%3}, [%4];"   \
        : "=r"((r)[0]), "=r"((r)[1]), "=r"((r)[2]), "=r"((r)[3]) : "r"(addr))
#define MMA(d, a, b0v, b1v)                                                        \
    asm volatile("mma.sync.aligned.m16n8k16.row.col.f32.bf16.bf16.f32 "            \
        "{%0,%1,%2,%3}, {%4,%5,%6,%7}, {%8,%9}, {%0,%1,%2,%3};"                    \
        : "+f"((d)[0]), "+f"((d)[1]), "+f"((d)[2]), "+f"((d)[3])                   \
        : "r"((a)[0]), "r"((a)[1]), "r"((a)[2]), "r"((a)[3]), "r"(b0v), "r"(b1v))

// ==================== scratch ====================
__device__ __align__(128) float g_feat[(size_t)BB * 64 * HW];
__device__ __align__(128) float g_dx  [(size_t)BB * 64 * HW];
__device__ __align__(128) __nv_bfloat16 g_in_h[(size_t)BB * HW * 64];     // NHWC hi of featmap_in
__device__ __align__(128) __nv_bfloat16 g_in_l[(size_t)BB * HW * 64];     // NHWC lo
__device__ __align__(128) __nv_bfloat16 g_actv_h[(size_t)BB * HW * 128];  // NHWC hi
__device__ __align__(128) __nv_bfloat16 g_actv_l[(size_t)BB * HW * 128];  // NHWC lo
__device__ __align__(128) float g_gb  [(size_t)BB * 128 * HW];            // gamma 0-63, beta 64-127
__device__ __align__(128) float g_table[BB * 9 * 35 * 128];
__device__ __align__(128) float g_codes[BB * 35 * 64];
__device__ __align__(128) float g_sums [BB * 64 * 36];
__device__ __align__(128) float g_cnt  [BB * 36];
__device__ __align__(128) float g_stats[2 * BB * 64];
__device__ __align__(128) __nv_bfloat16 g_w1m[9 * 2 * 128 * 64];          // [tap][prec][oc][ic]
__device__ __align__(128) __nv_bfloat16 g_w2m[9 * 2 * 2 * 128 * 64];      // [tap][kc][prec][oc][ic]

// ==================== small kernels ====================
__global__ void k_zero() {
    int i = blockIdx.x * 256 + threadIdx.x;
    if (i < BB * 64 * 36) g_sums[i] = 0.f;
    if (i < BB * 36)      g_cnt[i]  = 0.f;
}

// conv1 weights: [tap][prec][oc(128: 0-63=w_conv,64-127=w_c0)][ic(64)]
__global__ void k_wpack1(const float* __restrict__ wc, const float* __restrict__ wc0) {
    int i = blockIdx.x * 256 + threadIdx.x;
    if (i >= 9 * 2 * 128 * 64) return;
    int ic   = i & 63;
    int oc   = (i >> 6) & 127;
    int prec = (i >> 13) & 1;
    int tap  = i >> 14;
    const float* src = (oc < 64) ? wc : wc0;
    float wv = src[((oc & 63) * 64 + ic) * 9 + tap];
    __nv_bfloat16 hi = __float2bfloat16(wv);
    g_w1m[i] = prec ? __float2bfloat16(wv - __bfloat162float(hi)) : hi;
}

// conv2 weights: [tap][kc][prec][oc(128: 0-63=gamma,64-127=beta)][ic(64)]
__global__ void k_wpack2(const float* __restrict__ wg, const float* __restrict__ wb) {
    int i = blockIdx.x * 256 + threadIdx.x;
    if (i >= 9 * 2 * 2 * 128 * 64) return;
    int ic   = i & 63;
    int oc   = (i >> 6) & 127;
    int prec = (i >> 13) & 1;
    int kc   = (i >> 14) & 1;
    int tap  = i >> 15;
    const float* src = (oc < 64) ? wg : wb;
    float wv = src[((oc & 63) * 128 + kc * 64 + ic) * 9 + tap];
    __nv_bfloat16 hi = __float2bfloat16(wv);
    g_w2m[i] = prec ? __float2bfloat16(wv - __bfloat162float(hi)) : hi;
}

// NCHW fp32 -> NHWC bf16 hi/lo split (smem tile transpose, 64px x 64ch)
__global__ void k_split(const float* __restrict__ in) {
    __shared__ float t[64][65];
    int b = blockIdx.y;
    int p0 = blockIdx.x * 64;
    int tid = threadIdx.x;
    for (int i = tid; i < 64 * 64; i += 256) {
        int c = i >> 6, px = i & 63;
        t[c][px] = in[((size_t)(b * 64 + c)) * HW + p0 + px];
    }
    __syncthreads();
    for (int i = tid; i < 64 * 64; i += 256) {
        int px = i >> 6, c = i & 63;
        float v = t[c][px];
        __nv_bfloat16 hi = __float2bfloat16(v);
        __nv_bfloat16 lo = __float2bfloat16(v - __bfloat162float(hi));
        size_t o = (((size_t)b * HW + p0 + px) << 6) + c;
        g_in_h[o] = hi;
        g_in_l[o] = lo;
    }
}

// ==================== shared MMA constants ====================
static constexpr int SA_PREC = 132 * 144;        // 19008 B
static constexpr int SW_OFF  = 2 * SA_PREC;      // 38016
static constexpr int SW_PREC = 128 * 144;        // 18432
static constexpr int SMEM_MMA = SW_OFF + 2 * SW_PREC;  // 74880

// ==================== conv1+conv_c0: warp-MMA bf16x3 (IC=64, OC=128) ====================
__global__ void __launch_bounds__(256, 2)
k_conv1mma(const float* __restrict__ bc_, const float* __restrict__ bc0_) {
    extern __shared__ __align__(1024) char sm[];
    uint32_t sa = smem_u32(sm);
    uint32_t sw = sa + SW_OFF;
    int tid = threadIdx.x;
    int w = tid >> 5, l = tid & 31;
    int x0 = blockIdx.x * 128, y = blockIdx.y, b = blockIdx.z;
    int mrow = (w & 3) * 32, ncol = (w >> 2) * 64;

    float acc[2][8][4];
#pragma unroll
    for (int mt = 0; mt < 2; mt++)
#pragma unroll
        for (int nt = 0; nt < 8; nt++)
#pragma unroll
            for (int e = 0; e < 4; e++) acc[mt][nt][e] = 0.f;

    for (int dy = 0; dy < 3; dy++) {
        __syncthreads();
        int iy = y + dy - 1;
        bool rowok = ((unsigned)iy < 256u);
        // stage A strip: 2 prec x 130 rows x 8 x 16B (row = 64 bf16 = 128B)
        for (int idx = tid; idx < 2080; idx += 256) {
            int prec = idx >= 1040; int e = idx - (prec ? 1040 : 0);
            int j = e >> 3, ch = e & 7;
            int x = x0 - 1 + j;
            uint4 v = make_uint4(0, 0, 0, 0);
            if (rowok && (unsigned)x < 256u) {
                const __nv_bfloat16* src = prec ? g_in_l : g_in_h;
                v = *(const uint4*)(src + (((size_t)b * HW + iy * 256 + x) << 6) + ch * 8);
            }
            *(uint4*)(sm + prec * SA_PREC + j * 144 + ch * 16) = v;
        }
        for (int dx = 0; dx < 3; dx++) {
            int tap = dy * 3 + dx;
            __syncthreads();
            const uint4* wsrc = (const uint4*)g_w1m + (size_t)tap * 2048;
            for (int idx = tid; idx < 2048; idx += 256) {
                int prec = idx >> 10; int e = idx & 1023; int oc = e >> 3, ch = e & 7;
                uint4 v = wsrc[idx];
                *(uint4*)(sm + SW_OFF + prec * SW_PREC + oc * 144 + ch * 16) = v;
            }
            __syncthreads();

            uint32_t aBase = sa + (mrow + dx + (l & 15)) * 144 + (l >> 4) * 16;
            uint32_t bBase = sw + (ncol + ((l >> 4) << 3) + (l & 7)) * 144 + ((l >> 3) & 1) * 16;
#pragma unroll
            for (int ks = 0; ks < 4; ks++) {
                uint32_t ah[2][4], al[2][4];
                LDM4(ah[0], aBase + ks * 32);
                LDM4(ah[1], aBase + 16 * 144 + ks * 32);
                LDM4(al[0], aBase + SA_PREC + ks * 32);
                LDM4(al[1], aBase + SA_PREC + 16 * 144 + ks * 32);
#pragma unroll
                for (int np = 0; np < 4; np++) {
                    uint32_t bh[4], bl[4];
                    LDM4(bh, bBase + np * 16 * 144 + ks * 32);
                    LDM4(bl, bBase + SW_PREC + np * 16 * 144 + ks * 32);
#pragma unroll
                    for (int mt = 0; mt < 2; mt++) {
                        MMA(acc[mt][np * 2 + 0], ah[mt], bh[0], bh[1]);
                        MMA(acc[mt][np * 2 + 0], ah[mt], bl[0], bl[1]);
                        MMA(acc[mt][np * 2 + 0], al[mt], bh[0], bh[1]);
                        MMA(acc[mt][np * 2 + 1], ah[mt], bh[2], bh[3]);
                        MMA(acc[mt][np * 2 + 1], ah[mt], bl[2], bl[3]);
                        MMA(acc[mt][np * 2 + 1], al[mt], bh[2], bh[3]);
                    }
                }
            }
        }
    }

    // epilogue: oc<64 -> lrelu -> g_feat; oc>=64 -> raw -> g_dx
    int g = l >> 2, tg = l & 3;
#pragma unroll
    for (int nt = 0; nt < 8; nt++) {
        int oc0 = ncol + nt * 8 + tg * 2;
        bool isFeat = oc0 < 64;
        float bias0 = isFeat ? bc_[oc0] : bc0_[oc0 - 64];
        float bias1 = isFeat ? bc_[oc0 + 1] : bc0_[oc0 - 63];
        float* dst = isFeat ? g_feat : g_dx;
        int c0 = isFeat ? oc0 : oc0 - 64;
#pragma unroll
        for (int mt = 0; mt < 2; mt++) {
            int px = x0 + mrow + mt * 16 + g;
            size_t o0 = ((size_t)(b * 64 + c0)) * HW + y * 256 + px;
            float v0 = acc[mt][nt][0] + bias0;
            float v1 = acc[mt][nt][1] + bias1;
            float v2 = acc[mt][nt][2] + bias0;
            float v3 = acc[mt][nt][3] + bias1;
            if (isFeat) {
                v0 = v0 >= 0.f ? v0 : 0.2f * v0;
                v1 = v1 >= 0.f ? v1 : 0.2f * v1;
                v2 = v2 >= 0.f ? v2 : 0.2f * v2;
                v3 = v3 >= 0.f ? v3 : 0.2f * v3;
            }
            dst[o0]          = v0;
            dst[o0 + HW]     = v1;
            dst[o0 + 8]      = v2;
            dst[o0 + HW + 8] = v3;
        }
    }
}

// ==================== conv2: warp-MMA bf16x3 (IC=128, OC=128) ====================
__global__ void __launch_bounds__(256, 2)
k_conv2mma(const float* __restrict__ bg_, const float* __restrict__ bb_) {
    extern __shared__ __align__(1024) char sm[];
    uint32_t sa = smem_u32(sm);
    uint32_t sw = sa + SW_OFF;
    int tid = threadIdx.x;
    int w = tid >> 5, l = tid & 31;
    int x0 = blockIdx.x * 128, y = blockIdx.y, b = blockIdx.z;
    int mrow = (w & 3) * 32, ncol = (w >> 2) * 64;

    float acc[2][8][4];
#pragma unroll
    for (int mt = 0; mt < 2; mt++)
#pragma unroll
        for (int nt = 0; nt < 8; nt++)
#pragma unroll
            for (int e = 0; e < 4; e++) acc[mt][nt][e] = 0.f;

    for (int kc = 0; kc < 2; kc++) {
        for (int dy = 0; dy < 3; dy++) {
            __syncthreads();
            int iy = y + dy - 1;
            bool rowok = ((unsigned)iy < 256u);
            for (int idx = tid; idx < 2080; idx += 256) {
                int prec = idx >= 1040; int e = idx - (prec ? 1040 : 0);
                int j = e >> 3, ch = e & 7;
                int x = x0 - 1 + j;
                uint4 v = make_uint4(0, 0, 0, 0);
                if (rowok && (unsigned)x < 256u) {
                    const __nv_bfloat16* src = prec ? g_actv_l : g_actv_h;
                    v = *(const uint4*)(src + (((size_t)b * HW + iy * 256 + x) << 7) + kc * 64 + ch * 8);
                }
                *(uint4*)(sm + prec * SA_PREC + j * 144 + ch * 16) = v;
            }
            for (int dx = 0; dx < 3; dx++) {
                int tap = dy * 3 + dx;
                __syncthreads();
                const uint4* wsrc = (const uint4*)g_w2m + (size_t)(tap * 2 + kc) * 2048;
                for (int idx = tid; idx < 2048; idx += 256) {
                    int prec = idx >> 10; int e = idx & 1023; int oc = e >> 3, ch = e & 7;
                    uint4 v = wsrc[idx];
                    *(uint4*)(sm + SW_OFF + prec * SW_PREC + oc * 144 + ch * 16) = v;
                }
                __syncthreads();

                uint32_t aBase = sa + (mrow + dx + (l & 15)) * 144 + (l >> 4) * 16;
                uint32_t bBase = sw + (ncol + ((l >> 4) << 3) + (l & 7)) * 144 + ((l >> 3) & 1) * 16;
#pragma unroll
                for (int ks = 0; ks < 4; ks++) {
                    uint32_t ah[2][4], al[2][4];
                    LDM4(ah[0], aBase + ks * 32);
                    LDM4(ah[1], aBase + 16 * 144 + ks * 32);
                    LDM4(al[0], aBase + SA_PREC + ks * 32);
                    LDM4(al[1], aBase + SA_PREC + 16 * 144 + ks * 32);
#pragma unroll
                    for (int np = 0; np < 4; np++) {
                        uint32_t bh[4], bl[4];
                        LDM4(bh, bBase + np * 16 * 144 + ks * 32);
                        LDM4(bl, bBase + SW_PREC + np * 16 * 144 + ks * 32);
#pragma unroll
                        for (int mt = 0; mt < 2; mt++) {
                            MMA(acc[mt][np * 2 + 0], ah[mt], bh[0], bh[1]);
                            MMA(acc[mt][np * 2 + 0], ah[mt], bl[0], bl[1]);
                            MMA(acc[mt][np * 2 + 0], al[mt], bh[0], bh[1]);
                            MMA(acc[mt][np * 2 + 1], ah[mt], bh[2], bh[3]);
                            MMA(acc[mt][np * 2 + 1], ah[mt], bl[2], bl[3]);
                            MMA(acc[mt][np * 2 + 1], al[mt], bh[2], bh[3]);
                        }
                    }
                }
            }
        }
    }

    int g = l >> 2, tg = l & 3;
#pragma unroll
    for (int nt = 0; nt < 8; nt++) {
        int oc0 = ncol + nt * 8 + tg * 2;
        float bias0 = (oc0 < 64) ? bg_[oc0] : bb_[oc0 - 64];
        float bias1 = (oc0 + 1 < 64) ? bg_[oc0 + 1] : bb_[oc0 - 63];
#pragma unroll
        for (int mt = 0; mt < 2; mt++) {
            int px = x0 + mrow + mt * 16 + g;
            size_t o0 = ((size_t)(b * 128 + oc0)) * HW + y * 256 + px;
            g_gb[o0]          = acc[mt][nt][0] + bias0;
            g_gb[o0 + HW]     = acc[mt][nt][1] + bias1;
            g_gb[o0 + 8]      = acc[mt][nt][2] + bias0;
            g_gb[o0 + HW + 8] = acc[mt][nt][3] + bias1;
        }
    }
}

// ==================== instance-norm stats ====================
__global__ void k_stats() {
    int bc = blockIdx.x;
    int tid = threadIdx.x;
    const float4* p = (const float4*)(g_dx + (size_t)bc * HW);
    float s = 0.f, s2 = 0.f;
    for (int i = tid; i < HW / 4; i += 256) {
        float4 v = p[i];
        s  += v.x + v.y + v.z + v.w;
        s2 += v.x * v.x + v.y * v.y + v.z * v.z + v.w * v.w;
    }
    __shared__ float rs[256], rq[256];
    rs[tid] = s; rq[tid] = s2;
    __syncthreads();
    for (int o = 128; o > 0; o >>= 1) {
        if (tid < o) { rs[tid] += rs[tid + o]; rq[tid] += rq[tid + o]; }
        __syncthreads();
    }
    if (tid == 0) {
        float m = rs[0] * (1.f / HW);
        float var = rq[0] * (1.f / HW) - m * m;
        g_stats[bc] = m;
        g_stats[512 + bc] = rsqrtf(var + 1e-5f);
    }
}

// ==================== masked per-class mean pooling ====================
__global__ void k_pool(const int* __restrict__ seg, const float* __restrict__ bg,
                       const float* __restrict__ mask) {
    __shared__ float s_sum[64 * 36];
    __shared__ float s_cnt[36];
    int tid = threadIdx.x;
    for (int i = tid; i < 64 * 36; i += 256) s_sum[i] = 0.f;
    if (tid < 36) s_cnt[tid] = 0.f;
    __syncthreads();
    int b = blockIdx.y;
    int lane = tid & 31, cg = tid >> 5;
    int base = blockIdx.x * 4096;
    for (int p0 = 0; p0 < 4096; p0 += 32) {
        int p = base + p0 + lane;
        int s = seg[b * HW + p];
        bool q = (bg[b * HW + p] * (1.f - mask[b * HW + p])) > 0.f;
        if (q && cg == 0) atomicAdd(&s_cnt[s], 1.f);
        if (q) {
#pragma unroll
            for (int cc = 0; cc < 8; cc++) {
                int c = cg + cc * 8;
                float f = g_feat[((size_t)(b * 64 + c)) * HW + p];
                atomicAdd(&s_sum[c * 36 + s], f);
            }
        }
    }
    __syncthreads();
    for (int i = tid; i < 64 * 36; i += 256) {
        float v = s_sum[i];
        if (v != 0.f) atomicAdd(&g_sums[b * 2304 + i], v);
    }
    if (tid < 36 && s_cnt[tid] != 0.f) atomicAdd(&g_cnt[b * 36 + tid], s_cnt[tid]);
}

__global__ void k_codes() {
    int i = blockIdx.x * 256 + threadIdx.x;
    if (i >= BB * 35 * 64) return;
    int b = i / (35 * 64); int s = (i / 64) % 35; int f = i & 63;
    float cnt = g_cnt[b * 36 + s];
    bool keep = !(s >= 24 && s <= 33);
    float v = 0.f;
    if (cnt > 0.f && keep) v = g_sums[b * 2304 + f * 36 + s] / cnt;
    g_codes[i] = v;
}

__global__ void k_table(const float* __restrict__ w_sh) {
    int b = blockIdx.x / 9, k = blockIdx.x % 9;
    int o = threadIdx.x;  // 128
    __shared__ float swt[64][128];
    __shared__ float sc[64];
    for (int f = 0; f < 64; f++) swt[f][o] = w_sh[(o * 99 + f) * 9 + k];
    for (int s = 0; s < 35; s++) {
        __syncthreads();
        if (o < 64) sc[o] = g_codes[(b * 35 + s) * 64 + o];
        __syncthreads();
        float acc = w_sh[(o * 99 + 64 + s) * 9 + k];
#pragma unroll 8
        for (int f = 0; f < 64; f++)
            acc = fmaf(swt[f][o], sc[f], acc);
        g_table[((b * 9 + k) * 35 + s) * 128 + o] = acc;
    }
}

// ---------------- actv = relu(b_sh + table conv) -> NHWC bf16 hi/lo ----------------
__global__ void k_actv(const int* __restrict__ seg, const float* __restrict__ bg,
                       const float* __restrict__ bsh) {
    __shared__ int ns[324];
    int b = blockIdx.z;
    int x0 = blockIdx.x * 16, y0 = blockIdx.y * 16;
    int tid = threadIdx.x;
    for (int i = tid; i < 324; i += 256) {
        int r = i / 18, c = i % 18;
        int gy = y0 - 1 + r, gx = x0 - 1 + c;
        int v = -1;
        if ((unsigned)gy < 256u && (unsigned)gx < 256u) {
            int p = gy * 256 + gx;
            if (bg[b * HW + p] > 0.f) v = seg[b * HW + p];
        }
        ns[i] = v;
    }
    __syncthreads();
    int oq = tid & 31, pg = tid >> 5;
    const float4* T4 = (const float4*)g_table + (size_t)b * 9 * 35 * 32;
    float4 bias = ((const float4*)bsh)[oq];
    for (int pp = pg * 32; pp < pg * 32 + 32; pp++) {
        int ly = pp >> 4, lx = pp & 15;
        float4 a = bias;
#pragma unroll
        for (int ky = 0; ky < 3; ky++)
#pragma unroll
            for (int kx = 0; kx < 3; kx++) {
                int idx = ns[(ly + ky) * 18 + lx + kx];
                if (idx >= 0) {
                    float4 t = T4[((ky * 3 + kx) * 35 + idx) * 32 + oq];
                    a.x += t.x; a.y += t.y; a.z += t.z; a.w += t.w;
                }
            }
        a.x = fmaxf(a.x, 0.f); a.y = fmaxf(a.y, 0.f);
        a.z = fmaxf(a.z, 0.f); a.w = fmaxf(a.w, 0.f);
        __nv_bfloat16 h0 = __float2bfloat16(a.x), h1 = __float2bfloat16(a.y);
        __nv_bfloat16 h2 = __float2bfloat16(a.z), h3 = __float2bfloat16(a.w);
        __nv_bfloat16 l0 = __float2bfloat16(a.x - __bfloat162float(h0));
        __nv_bfloat16 l1 = __float2bfloat16(a.y - __bfloat162float(h1));
        __nv_bfloat16 l2 = __float2bfloat16(a.z - __bfloat162float(h2));
        __nv_bfloat16 l3 = __float2bfloat16(a.w - __bfloat162float(h3));
        int gp = (y0 + ly) * 256 + x0 + lx;
        size_t base = (((size_t)b * HW + gp) << 7) + oq * 4;
        uint2 hv, lv;
        hv.x = (uint32_t)__bfloat16_as_ushort(h0) | ((uint32_t)__bfloat16_as_ushort(h1) << 16);
        hv.y = (uint32_t)__bfloat16_as_ushort(h2) | ((uint32_t)__bfloat16_as_ushort(h3) << 16);
        lv.x = (uint32_t)__bfloat16_as_ushort(l0) | ((uint32_t)__bfloat16_as_ushort(l1) << 16);
        lv.y = (uint32_t)__bfloat16_as_ushort(l2) | ((uint32_t)__bfloat16_as_ushort(l3) << 16);
        *(uint2*)(g_actv_h + base) = hv;
        *(uint2*)(g_actv_l + base) = lv;
    }
}

// ---------------- final ----------------
__global__ void k_final(float* __restrict__ out) {
    size_t gi = (size_t)blockIdx.x * 256 + threadIdx.x;
    size_t e = gi * 4;
    int b = (int)(e / ((size_t)64 * HW));
    int c = (int)((e / HW) & 63);
    size_t p = e % HW;
    float4 dx = ((const float4*)g_dx)[gi];
    float4 ga = ((const float4*)g_gb)[((size_t)(b * 128 + c) * HW + p) / 4];
    float4 be = ((const float4*)g_gb)[((size_t)(b * 128 + 64 + c) * HW + p) / 4];
    float m = g_stats[b * 64 + c], r = g_stats[512 + b * 64 + c];
    float4 o;
    float v;
    v = (dx.x - m) * r * (1.f + ga.x) + be.x; o.x = v >= 0.f ? v : 0.2f * v;
    v = (dx.y - m) * r * (1.f + ga.y) + be.y; o.y = v >= 0.f ? v : 0.2f * v;
    v = (dx.z - m) * r * (1.f + ga.z) + be.z; o.z = v >= 0.f ? v : 0.2f * v;
    v = (dx.w - m) * r * (1.f + ga.w) + be.w; o.w = v >= 0.f ? v : 0.2f * v;
    ((float4*)out)[gi] = o;
}

// ==================== host ====================
extern "C" void kernel_launch(void* const* d_in, const int* in_sizes, int n_in,
                              void* d_out, int out_size) {
    const float* featmap_in = (const float*)d_in[0];
    const int*   seg        = (const int*)  d_in[1];
    const float* bg         = (const float*)d_in[2];
    const float* mask       = (const float*)d_in[3];
    const float* w_conv     = (const float*)d_in[4];
    const float* b_conv     = (const float*)d_in[5];
    const float* w_c0       = (const float*)d_in[6];
    const float* b_c0       = (const float*)d_in[7];
    const float* w_sh       = (const float*)d_in[8];
    const float* b_sh       = (const float*)d_in[9];
    const float* w_g        = (const float*)d_in[10];
    const float* b_g        = (const float*)d_in[11];
    const float* w_b        = (const float*)d_in[12];
    const float* b_b        = (const float*)d_in[13];

    cudaFuncSetAttribute(k_conv1mma, cudaFuncAttributeMaxDynamicSharedMemorySize, SMEM_MMA);
    cudaFuncSetAttribute(k_conv2mma, cudaFuncAttributeMaxDynamicSharedMemorySize, SMEM_MMA);

    k_zero<<<72, 256>>>();
    k_wpack1<<<576, 256>>>(w_conv, w_c0);
    k_wpack2<<<1152, 256>>>(w_g, w_b);
    k_split<<<dim3(1024, 8), 256>>>(featmap_in);

    // conv1 (lrelu -> g_feat) + conv_c0 (raw -> g_dx) via warp-MMA
    k_conv1mma<<<dim3(2, 256, 8), 256, SMEM_MMA>>>(b_conv, b_c0);

    k_stats<<<512, 256>>>();
    k_pool<<<dim3(16, 8), 256>>>(seg, bg, mask);
    k_codes<<<70, 256>>>();
    k_table<<<72, 128>>>(w_sh);
    k_actv<<<dim3(16, 16, 8), 256>>>(seg, bg, b_sh);

    // gamma/beta via warp-MMA bf16x3
    k_conv2mma<<<dim3(2, 256, 8), 256, SMEM_MMA>>>(b_g, b_b);

    k_final<<<32768, 256>>>((float*)d_out);
}